// round 2
// baseline (speedup 1.0000x reference)
#include <cuda_runtime.h>
#include <cuda_bf16.h>
#include <cstdint>

// ---------------------------------------------------------------------------
// BiLSTM: B=32, T=512, I=512, H=512, gates=4H=2048, out (32,512,1024) fp32
//
// Phase A: gx[b,t,c] = sum_i x[b,t,i]*Wx[c,i] + bx[c]   (tiled SIMT GEMM)
// Phase B: persistent scan kernel, 2 directions in parallel (64 blocks each),
//          per-direction spin barrier each timestep, h double-buffered in
//          global, c in registers, Wh tile resident in smem.
// ---------------------------------------------------------------------------

#define Bsz 32
#define Tsz 512
#define Isz 512
#define Hsz 512
#define G4  2048

// 128 MiB scratch for gx, plus h double buffers and barrier counters.
__device__ float g_gx[(size_t)Bsz * Tsz * G4];
__device__ float g_h[2][2][Hsz * Bsz];   // [dir][parity][j*32 + b]
__device__ unsigned g_ctr[2];

// ---- packed f32x2 helpers --------------------------------------------------
__device__ __forceinline__ unsigned long long fma2(unsigned long long a,
                                                   unsigned long long b,
                                                   unsigned long long c) {
    unsigned long long d;
    asm("fma.rn.f32x2 %0, %1, %2, %3;" : "=l"(d) : "l"(a), "l"(b), "l"(c));
    return d;
}
__device__ __forceinline__ unsigned long long pack2(float lo, float hi) {
    unsigned long long r;
    asm("mov.b64 %0, {%1, %2};" : "=l"(r) : "f"(lo), "f"(hi));
    return r;
}
__device__ __forceinline__ float2 unpack2(unsigned long long v) {
    float2 r;
    asm("mov.b64 {%0, %1}, %2;" : "=f"(r.x), "=f"(r.y) : "l"(v));
    return r;
}

// ---------------------------------------------------------------------------
// Phase A: gx = x @ Wx^T + bx
// A: [M=16384][K=512] row-major, W: [N=2048][K=512] row-major.
// 64x64 block tile, TK=16, 256 threads, 4x4 micro-tile, f32x2 accumulation.
// ---------------------------------------------------------------------------
__global__ __launch_bounds__(256) void gemm_gx(const float* __restrict__ A,
                                               const float* __restrict__ W,
                                               const float* __restrict__ bx) {
    __shared__ __align__(16) float As[16][68];
    __shared__ __align__(16) float Bs[16][68];

    const int bm = blockIdx.y * 64;
    const int bn = blockIdx.x * 64;
    const int tid = threadIdx.x;
    const int lr = tid >> 2;   // 0..63: row within tile
    const int lc = tid & 3;    // 0..3 : which float4 along k
    const int ty = tid >> 4;   // 0..15: m sub-tile
    const int tx = tid & 15;   // 0..15: n sub-tile

    unsigned long long acc[4][2];
#pragma unroll
    for (int i = 0; i < 4; i++) { acc[i][0] = 0ull; acc[i][1] = 0ull; }

    for (int kt = 0; kt < Isz; kt += 16) {
        float4 a = *(const float4*)&A[(size_t)(bm + lr) * Isz + kt + lc * 4];
        float4 w = *(const float4*)&W[(size_t)(bn + lr) * Isz + kt + lc * 4];
        As[lc * 4 + 0][lr] = a.x;
        As[lc * 4 + 1][lr] = a.y;
        As[lc * 4 + 2][lr] = a.z;
        As[lc * 4 + 3][lr] = a.w;
        Bs[lc * 4 + 0][lr] = w.x;
        Bs[lc * 4 + 1][lr] = w.y;
        Bs[lc * 4 + 2][lr] = w.z;
        Bs[lc * 4 + 3][lr] = w.w;
        __syncthreads();
#pragma unroll
        for (int kk = 0; kk < 16; kk++) {
            float4 a4 = *(const float4*)&As[kk][ty * 4];
            ulonglong2 b2 = *(const ulonglong2*)&Bs[kk][tx * 4];
            unsigned long long am;
            am = pack2(a4.x, a4.x);
            acc[0][0] = fma2(b2.x, am, acc[0][0]);
            acc[0][1] = fma2(b2.y, am, acc[0][1]);
            am = pack2(a4.y, a4.y);
            acc[1][0] = fma2(b2.x, am, acc[1][0]);
            acc[1][1] = fma2(b2.y, am, acc[1][1]);
            am = pack2(a4.z, a4.z);
            acc[2][0] = fma2(b2.x, am, acc[2][0]);
            acc[2][1] = fma2(b2.y, am, acc[2][1]);
            am = pack2(a4.w, a4.w);
            acc[3][0] = fma2(b2.x, am, acc[3][0]);
            acc[3][1] = fma2(b2.y, am, acc[3][1]);
        }
        __syncthreads();
    }

    float4 bxv = *(const float4*)&bx[bn + tx * 4];
#pragma unroll
    for (int mm = 0; mm < 4; mm++) {
        float2 p0 = unpack2(acc[mm][0]);
        float2 p1 = unpack2(acc[mm][1]);
        float4 r;
        r.x = p0.x + bxv.x;
        r.y = p0.y + bxv.y;
        r.z = p1.x + bxv.z;
        r.w = p1.y + bxv.w;
        *(float4*)&g_gx[(size_t)(bm + ty * 4 + mm) * G4 + bn + tx * 4] = r;
    }
}

// ---------------------------------------------------------------------------
// Phase B: persistent bidirectional scan.
// 128 blocks: blocks [0,64) forward, [64,128) backward.
// Block covers 8 hidden units (j) x 32 batches; thread = (warp jj, lane b).
// smem: Wh tile (8 j x 4 gates x 512 k) interleaved as [jj][k][g] = 64KB,
//       h staging [k][b] = 64KB.
// ---------------------------------------------------------------------------
#define JPB 8
#define NBLK_DIR 64

__global__ __launch_bounds__(256, 1) void lstm_scan(const float* __restrict__ Wh,
                                                    const float* __restrict__ bh,
                                                    float* __restrict__ out) {
    extern __shared__ float smem[];
    float* w_s = smem;                 // JPB*512*4 = 16384 floats
    float* h_s = smem + JPB * 512 * 4; // 512*32    = 16384 floats

    const int dir = blockIdx.x >> 6;
    const int sub = blockIdx.x & 63;
    const int j0 = sub * JPB;
    const int tid = threadIdx.x;
    const int jj = tid >> 5;
    const int b = tid & 31;
    const int j = j0 + jj;

    // Load Wh tile once: w_s[(jj*512 + k)*4 + g] = Wh[g*512 + j0+jj][k]
    for (int i = tid; i < JPB * 512; i += 256) {
        int jj2 = i >> 9;
        int k = i & 511;
        float4 w;
        w.x = Wh[(size_t)(0 * Hsz + j0 + jj2) * Hsz + k];
        w.y = Wh[(size_t)(1 * Hsz + j0 + jj2) * Hsz + k];
        w.z = Wh[(size_t)(2 * Hsz + j0 + jj2) * Hsz + k];
        w.w = Wh[(size_t)(3 * Hsz + j0 + jj2) * Hsz + k];
        *(float4*)&w_s[(size_t)i * 4] = w;
    }
    const float bh_i = bh[0 * Hsz + j];
    const float bh_f = bh[1 * Hsz + j];
    const float bh_g = bh[2 * Hsz + j];
    const float bh_o = bh[3 * Hsz + j];

    unsigned* ctr = &g_ctr[dir];
    float c_state = 0.0f;
    const float* wrow = &w_s[(size_t)jj * 512 * 4];
    __syncthreads();

    for (int t = 0; t < Tsz; t++) {
        const int te = dir ? (Tsz - 1 - t) : t;  // gx read index
        const float* hb_r = &g_h[dir][t & 1][0];
        float* hb_w = &g_h[dir][(t + 1) & 1][0];

        // Stage h into smem (straight copy: both are [j][b] layout).
        {
            const float4* src = (const float4*)hb_r;
            float4* dst = (float4*)h_s;
            for (int i = tid; i < (Hsz * Bsz) / 4; i += 256)
                dst[i] = __ldcg(src + i);
        }
        // Prefetch gx for this (b, t, j) before the barrier.
        const float* gxp = g_gx + ((size_t)b * Tsz + te) * G4 + j;
        float gi = gxp[0 * Hsz];
        float gf = gxp[1 * Hsz];
        float gg = gxp[2 * Hsz];
        float go = gxp[3 * Hsz];
        __syncthreads();

        unsigned long long acc_if = pack2(gi + bh_i, gf + bh_f);
        unsigned long long acc_go = pack2(gg + bh_g, go + bh_o);
#pragma unroll 8
        for (int k = 0; k < Hsz; k++) {
            float h = h_s[k * 32 + b];
            unsigned long long h2 = pack2(h, h);
            ulonglong2 w2 = *(const ulonglong2*)&wrow[(size_t)k * 4];
            acc_if = fma2(w2.x, h2, acc_if);
            acc_go = fma2(w2.y, h2, acc_go);
        }
        float2 vif = unpack2(acc_if);
        float2 vgo = unpack2(acc_go);
        float it = 1.0f / (1.0f + expf(-vif.x));
        float ft = 1.0f / (1.0f + expf(-vif.y));
        float gt = tanhf(vgo.x);
        float ot = 1.0f / (1.0f + expf(-vgo.y));
        c_state = c_state * ft + it * gt;
        float hy = ot * tanhf(c_state);

        hb_w[j * 32 + b] = hy;                                   // coalesced
        out[((size_t)b * Tsz + t) * (2 * Hsz) + dir * Hsz + j] = hy;

        // Release all stores, then per-direction barrier.
        __threadfence();
        __syncthreads();
        if (tid == 0) {
            atomicAdd(ctr, 1u);
            unsigned targ = (unsigned)(NBLK_DIR * (t + 1));
            while (*((volatile unsigned*)ctr) < targ) {
                __nanosleep(32);
            }
        }
        __syncthreads();
    }
}

// ---------------------------------------------------------------------------
extern "C" void kernel_launch(void* const* d_in, const int* in_sizes, int n_in,
                              void* d_out, int out_size) {
    const float* x = (const float*)d_in[0];   // (32,512,512)
    const float* Wx = (const float*)d_in[1];  // (2048,512)
    const float* bx = (const float*)d_in[2];  // (2048)
    const float* Wh = (const float*)d_in[3];  // (2048,512)
    const float* bh = (const float*)d_in[4];  // (2048)
    float* out = (float*)d_out;               // (32,512,1024)

    // Reset recurrent state + barrier counters (graph-capturable memsets).
    void* p_h = nullptr;
    void* p_ctr = nullptr;
    cudaGetSymbolAddress(&p_h, g_h);
    cudaGetSymbolAddress(&p_ctr, g_ctr);
    cudaMemsetAsync(p_h, 0, sizeof(g_h), 0);
    cudaMemsetAsync(p_ctr, 0, sizeof(g_ctr), 0);

    // Phase A: input projection GEMM.
    dim3 grid(G4 / 64, (Bsz * Tsz) / 64);
    gemm_gx<<<grid, 256>>>(x, Wx, bx);

    // Phase B: persistent scan (both directions concurrently).
    const int smem_bytes = (JPB * 512 * 4 + Hsz * Bsz) * (int)sizeof(float);
    static int attr_done = 0;
    cudaFuncSetAttribute(lstm_scan, cudaFuncAttributeMaxDynamicSharedMemorySize,
                         smem_bytes);
    (void)attr_done;
    lstm_scan<<<2 * NBLK_DIR, 256, smem_bytes>>>(Wh, bh, out);
}

// round 5
// speedup vs baseline: 1.1962x; 1.1962x over previous
#include <cuda_runtime.h>
#include <cuda_bf16.h>
#include <cstdint>

// ---------------------------------------------------------------------------
// BiLSTM: B=32, T=512, I=512, H=512, gates=4H=2048, out (32,512,1024) fp32
//
// Phase A: gx[b,t,c] = sum_i x[b,t,i]*Wx[c,i] + bx[c]   (tiled SIMT GEMM)
// Phase B: persistent scan, 2 dirs x 64 blocks. Register micro-tiled GEMV:
//   thread = (kq, j, bg): 1 hidden unit x 4 gates x 4 batches, k split 4-way.
//   w pre-duplicated (w,w) in smem (broadcast LDS), h as natural float4 pairs.
//   Crossbar ~3 cyc/warp-k < FMA floor 4096 cyc/step -> FMA-bound loop.
// ---------------------------------------------------------------------------

#define Bsz 32
#define Tsz 512
#define Isz 512
#define Hsz 512
#define G4  2048

#define JPB 8          // hidden units per block
#define NBLK_DIR 64    // blocks per direction
#define WJ 4104        // padded per-j stride in w_s (512*8 + 8 floats)

__device__ float g_gx[(size_t)Bsz * Tsz * G4];
__device__ float g_h[2][2][Hsz * Bsz];   // [dir][parity][j*32 + b]
__device__ unsigned g_ctr[2];

// ---- packed f32x2 helpers --------------------------------------------------
__device__ __forceinline__ unsigned long long fma2(unsigned long long a,
                                                   unsigned long long b,
                                                   unsigned long long c) {
    unsigned long long d;
    asm("fma.rn.f32x2 %0, %1, %2, %3;" : "=l"(d) : "l"(a), "l"(b), "l"(c));
    return d;
}
__device__ __forceinline__ unsigned long long add2(unsigned long long a,
                                                   unsigned long long b) {
    unsigned long long d;
    asm("add.rn.f32x2 %0, %1, %2;" : "=l"(d) : "l"(a), "l"(b));
    return d;
}
__device__ __forceinline__ unsigned long long pack2(float lo, float hi) {
    unsigned long long r;
    asm("mov.b64 %0, {%1, %2};" : "=l"(r) : "f"(lo), "f"(hi));
    return r;
}
__device__ __forceinline__ float2 unpack2(unsigned long long v) {
    float2 r;
    asm("mov.b64 {%0, %1}, %2;" : "=f"(r.x), "=f"(r.y) : "l"(v));
    return r;
}

__device__ __forceinline__ float fast_sigmoid(float x) {
    return __fdividef(1.0f, 1.0f + __expf(-x));
}
__device__ __forceinline__ float fast_tanh(float x) {
    return 1.0f - 2.0f * __fdividef(1.0f, __expf(2.0f * x) + 1.0f);
}

// ---------------------------------------------------------------------------
// Phase A: gx = x @ Wx^T + bx  (unchanged from round 2)
// ---------------------------------------------------------------------------
__global__ __launch_bounds__(256) void gemm_gx(const float* __restrict__ A,
                                               const float* __restrict__ W,
                                               const float* __restrict__ bx) {
    __shared__ __align__(16) float As[16][68];
    __shared__ __align__(16) float Bs[16][68];

    const int bm = blockIdx.y * 64;
    const int bn = blockIdx.x * 64;
    const int tid = threadIdx.x;
    const int lr = tid >> 2;
    const int lc = tid & 3;
    const int ty = tid >> 4;
    const int tx = tid & 15;

    unsigned long long acc[4][2];
#pragma unroll
    for (int i = 0; i < 4; i++) { acc[i][0] = 0ull; acc[i][1] = 0ull; }

    for (int kt = 0; kt < Isz; kt += 16) {
        float4 a = *(const float4*)&A[(size_t)(bm + lr) * Isz + kt + lc * 4];
        float4 w = *(const float4*)&W[(size_t)(bn + lr) * Isz + kt + lc * 4];
        As[lc * 4 + 0][lr] = a.x;
        As[lc * 4 + 1][lr] = a.y;
        As[lc * 4 + 2][lr] = a.z;
        As[lc * 4 + 3][lr] = a.w;
        Bs[lc * 4 + 0][lr] = w.x;
        Bs[lc * 4 + 1][lr] = w.y;
        Bs[lc * 4 + 2][lr] = w.z;
        Bs[lc * 4 + 3][lr] = w.w;
        __syncthreads();
#pragma unroll
        for (int kk = 0; kk < 16; kk++) {
            float4 a4 = *(const float4*)&As[kk][ty * 4];
            ulonglong2 b2 = *(const ulonglong2*)&Bs[kk][tx * 4];
            unsigned long long am;
            am = pack2(a4.x, a4.x);
            acc[0][0] = fma2(b2.x, am, acc[0][0]);
            acc[0][1] = fma2(b2.y, am, acc[0][1]);
            am = pack2(a4.y, a4.y);
            acc[1][0] = fma2(b2.x, am, acc[1][0]);
            acc[1][1] = fma2(b2.y, am, acc[1][1]);
            am = pack2(a4.z, a4.z);
            acc[2][0] = fma2(b2.x, am, acc[2][0]);
            acc[2][1] = fma2(b2.y, am, acc[2][1]);
            am = pack2(a4.w, a4.w);
            acc[3][0] = fma2(b2.x, am, acc[3][0]);
            acc[3][1] = fma2(b2.y, am, acc[3][1]);
        }
        __syncthreads();
    }

    float4 bxv = *(const float4*)&bx[bn + tx * 4];
#pragma unroll
    for (int mm = 0; mm < 4; mm++) {
        float2 p0 = unpack2(acc[mm][0]);
        float2 p1 = unpack2(acc[mm][1]);
        float4 r;
        r.x = p0.x + bxv.x;
        r.y = p0.y + bxv.y;
        r.z = p1.x + bxv.z;
        r.w = p1.y + bxv.w;
        *(float4*)&g_gx[(size_t)(bm + ty * 4 + mm) * G4 + bn + tx * 4] = r;
    }
}

// ---------------------------------------------------------------------------
// Phase B: persistent scan with register micro-tiling.
//   smem: w_s[j][k][8] (dup pairs, padded) = 131.3KB; h_s[k][b] fp32 = 64KB
//   thread tid: kq=tid>>6 (k quarter), r=tid&63: j=r>>3, bg=r&7 (4 batches)
// ---------------------------------------------------------------------------
__global__ __launch_bounds__(256, 1) void lstm_scan(const float* __restrict__ Wh,
                                                    const float* __restrict__ bh,
                                                    float* __restrict__ out) {
    extern __shared__ float smem[];
    float* w_s = smem;                 // JPB * WJ floats
    float* h_s = smem + JPB * WJ;      // 512*32 floats (also reduce scratch)

    const int dir = blockIdx.x >> 6;
    const int sub = blockIdx.x & 63;
    const int j0 = sub * JPB;
    const int tid = threadIdx.x;
    const int kq = tid >> 6;       // 0..3
    const int r = tid & 63;
    const int j = r >> 3;          // 0..7
    const int bg = r & 7;          // 0..7
    const int b0 = bg * 4;
    const int k0 = kq * 128;

    // Load Wh tile once, duplicated (w,w) pairs per gate.
    for (int i = tid; i < JPB * 512; i += 256) {
        int j2 = i >> 9;
        int k = i & 511;
        float w0 = Wh[(size_t)(0 * Hsz + j0 + j2) * Hsz + k];
        float w1 = Wh[(size_t)(1 * Hsz + j0 + j2) * Hsz + k];
        float w2 = Wh[(size_t)(2 * Hsz + j0 + j2) * Hsz + k];
        float w3 = Wh[(size_t)(3 * Hsz + j0 + j2) * Hsz + k];
        float* d = &w_s[(size_t)j2 * WJ + k * 8];
        *(float4*)&d[0] = make_float4(w0, w0, w1, w1);
        *(float4*)&d[4] = make_float4(w2, w2, w3, w3);
    }

    // Owner-thread (kq==0) per-gate biases.
    float bh_g[4];
#pragma unroll
    for (int g = 0; g < 4; g++) bh_g[g] = bh[g * Hsz + j0 + j];

    unsigned* ctr = &g_ctr[dir];
    float cst[4] = {0.f, 0.f, 0.f, 0.f};
    __syncthreads();

    for (int t = 0; t < Tsz; t++) {
        const int te = dir ? (Tsz - 1 - t) : t;

        // Prefetch gx for this thread's 4 gates x 4 batches (owners only).
        float gxr[16];
        if (kq == 0) {
#pragma unroll
            for (int bb = 0; bb < 4; bb++) {
                const float* gp =
                    g_gx + ((size_t)(b0 + bb) * Tsz + te) * G4 + j0 + j;
#pragma unroll
                for (int g = 0; g < 4; g++)
                    gxr[g * 4 + bb] = __ldcg(gp + g * Hsz);
            }
        }

        // Stage h(t) into smem [k][b].
        {
            const float4* src = (const float4*)&g_h[dir][t & 1][0];
            float4* dst = (float4*)h_s;
#pragma unroll 4
            for (int i = tid; i < (Hsz * Bsz) / 4; i += 256)
                dst[i] = __ldcg(src + i);
        }
        __syncthreads();

        // k-quarter GEMV: acc[g][bp], bp = batch pair.
        unsigned long long a00 = 0, a01 = 0, a10 = 0, a11 = 0;
        unsigned long long a20 = 0, a21 = 0, a30 = 0, a31 = 0;
        const float* wp = &w_s[(size_t)j * WJ + k0 * 8];
        const float* hp = &h_s[k0 * 32 + b0];
#pragma unroll 4
        for (int kk = 0; kk < 128; kk++) {
            float4 h4 = *(const float4*)hp;
            ulonglong2 wd01 = *(const ulonglong2*)wp;
            ulonglong2 wd23 = *(const ulonglong2*)(wp + 4);
            unsigned long long hp0 = pack2(h4.x, h4.y);
            unsigned long long hp1 = pack2(h4.z, h4.w);
            a00 = fma2(wd01.x, hp0, a00);
            a01 = fma2(wd01.x, hp1, a01);
            a10 = fma2(wd01.y, hp0, a10);
            a11 = fma2(wd01.y, hp1, a11);
            a20 = fma2(wd23.x, hp0, a20);
            a21 = fma2(wd23.x, hp1, a21);
            a30 = fma2(wd23.y, hp0, a30);
            a31 = fma2(wd23.y, hp1, a31);
            wp += 8;
            hp += 32;
        }
        __syncthreads();  // h_s reads done; safe to reuse as scratch

        // k-split reduction via smem scratch (reuse h_s).
        float* red = h_s;
        if (kq > 0) {
            ulonglong2* d = (ulonglong2*)&red[(size_t)((kq - 1) * 64 + r) * 16];
            d[0] = make_ulonglong2(a00, a01);
            d[1] = make_ulonglong2(a10, a11);
            d[2] = make_ulonglong2(a20, a21);
            d[3] = make_ulonglong2(a30, a31);
        }
        __syncthreads();

        if (kq == 0) {
#pragma unroll
            for (int p = 0; p < 3; p++) {
                const ulonglong2* s =
                    (const ulonglong2*)&red[(size_t)(p * 64 + r) * 16];
                ulonglong2 s0 = s[0], s1 = s[1], s2 = s[2], s3 = s[3];
                a00 = add2(a00, s0.x);
                a01 = add2(a01, s0.y);
                a10 = add2(a10, s1.x);
                a11 = add2(a11, s1.y);
                a20 = add2(a20, s2.x);
                a21 = add2(a21, s2.y);
                a30 = add2(a30, s3.x);
                a31 = add2(a31, s3.y);
            }
            float gate[4][4];
            float2 v;
            v = unpack2(a00); gate[0][0] = v.x; gate[0][1] = v.y;
            v = unpack2(a01); gate[0][2] = v.x; gate[0][3] = v.y;
            v = unpack2(a10); gate[1][0] = v.x; gate[1][1] = v.y;
            v = unpack2(a11); gate[1][2] = v.x; gate[1][3] = v.y;
            v = unpack2(a20); gate[2][0] = v.x; gate[2][1] = v.y;
            v = unpack2(a21); gate[2][2] = v.x; gate[2][3] = v.y;
            v = unpack2(a30); gate[3][0] = v.x; gate[3][1] = v.y;
            v = unpack2(a31); gate[3][2] = v.x; gate[3][3] = v.y;

            float hv[4];
#pragma unroll
            for (int bb = 0; bb < 4; bb++) {
                float gi = gate[0][bb] + gxr[0 * 4 + bb] + bh_g[0];
                float gf = gate[1][bb] + gxr[1 * 4 + bb] + bh_g[1];
                float gg = gate[2][bb] + gxr[2 * 4 + bb] + bh_g[2];
                float go = gate[3][bb] + gxr[3 * 4 + bb] + bh_g[3];
                float it = fast_sigmoid(gi);
                float ft = fast_sigmoid(gf);
                float gt = fast_tanh(gg);
                float ot = fast_sigmoid(go);
                cst[bb] = cst[bb] * ft + it * gt;
                hv[bb] = ot * fast_tanh(cst[bb]);
            }
            // h(t+1) buffer, coalesced float4 per thread.
            *(float4*)&g_h[dir][(t + 1) & 1][(j0 + j) * 32 + b0] =
                make_float4(hv[0], hv[1], hv[2], hv[3]);
            // Output.
#pragma unroll
            for (int bb = 0; bb < 4; bb++)
                out[((size_t)(b0 + bb) * Tsz + t) * (2 * Hsz) + dir * Hsz +
                    j0 + j] = hv[bb];
        }

        // Release h stores, then per-direction barrier.
        __threadfence();
        __syncthreads();
        if (tid == 0) {
            atomicAdd(ctr, 1u);
            unsigned targ = (unsigned)(NBLK_DIR * (t + 1));
            while (*((volatile unsigned*)ctr) < targ) {
                __nanosleep(32);
            }
        }
        __syncthreads();
    }
}

// ---------------------------------------------------------------------------
extern "C" void kernel_launch(void* const* d_in, const int* in_sizes, int n_in,
                              void* d_out, int out_size) {
    const float* x = (const float*)d_in[0];   // (32,512,512)
    const float* Wx = (const float*)d_in[1];  // (2048,512)
    const float* bx = (const float*)d_in[2];  // (2048)
    const float* Wh = (const float*)d_in[3];  // (2048,512)
    const float* bh = (const float*)d_in[4];  // (2048)
    float* out = (float*)d_out;               // (32,512,1024)

    void* p_h = nullptr;
    void* p_ctr = nullptr;
    cudaGetSymbolAddress(&p_h, g_h);
    cudaGetSymbolAddress(&p_ctr, g_ctr);
    cudaMemsetAsync(p_h, 0, sizeof(g_h), 0);
    cudaMemsetAsync(p_ctr, 0, sizeof(g_ctr), 0);

    // Phase A: input projection GEMM.
    dim3 grid(G4 / 64, (Bsz * Tsz) / 64);
    gemm_gx<<<grid, 256>>>(x, Wx, bx);

    // Phase B: persistent scan.
    const int smem_bytes = (JPB * WJ + Hsz * Bsz) * (int)sizeof(float);
    cudaFuncSetAttribute(lstm_scan, cudaFuncAttributeMaxDynamicSharedMemorySize,
                         smem_bytes);
    lstm_scan<<<2 * NBLK_DIR, 256, smem_bytes>>>(Wh, bh, out);
}

// round 6
// speedup vs baseline: 1.2435x; 1.0395x over previous
#include <cuda_runtime.h>
#include <cuda_bf16.h>
#include <cstdint>

// ---------------------------------------------------------------------------
// BiLSTM: B=32, T=512, I=512, H=512, gates=4H=2048, out (32,512,1024) fp32
//
// Phase A: gx = x @ Wx^T + bx. 128x128 tile, 8x8 micro-tile, K-tile 8,
//          double-buffered smem, f32x2 packed FMA. FMA-pipe-bound.
// Phase B: persistent scan, 2 dirs x 64 blocks x 512 threads (16 warps for
//          latency hiding). k split 8-way; register micro-tile 1j x 4g x 4b;
//          w pre-duplicated (w,w) pairs in smem; smem k-split reduction;
//          per-direction global spin barrier each step.
// ---------------------------------------------------------------------------

#define Bsz 32
#define Tsz 512
#define Isz 512
#define Hsz 512
#define G4  2048

#define JPB 8          // hidden units per block
#define NBLK_DIR 64    // blocks per direction
#define WJ 4104        // padded per-j stride in w_s (512*8 + 8 floats)

__device__ float g_gx[(size_t)Bsz * Tsz * G4];
__device__ float g_h[2][2][Hsz * Bsz];   // [dir][parity][j*32 + b]
__device__ unsigned g_ctr[2];

// ---- packed f32x2 helpers --------------------------------------------------
__device__ __forceinline__ unsigned long long fma2(unsigned long long a,
                                                   unsigned long long b,
                                                   unsigned long long c) {
    unsigned long long d;
    asm("fma.rn.f32x2 %0, %1, %2, %3;" : "=l"(d) : "l"(a), "l"(b), "l"(c));
    return d;
}
__device__ __forceinline__ unsigned long long add2(unsigned long long a,
                                                   unsigned long long b) {
    unsigned long long d;
    asm("add.rn.f32x2 %0, %1, %2;" : "=l"(d) : "l"(a), "l"(b));
    return d;
}
__device__ __forceinline__ unsigned long long pack2(float lo, float hi) {
    unsigned long long r;
    asm("mov.b64 %0, {%1, %2};" : "=l"(r) : "f"(lo), "f"(hi));
    return r;
}
__device__ __forceinline__ float2 unpack2(unsigned long long v) {
    float2 r;
    asm("mov.b64 {%0, %1}, %2;" : "=f"(r.x), "=f"(r.y) : "l"(v));
    return r;
}

__device__ __forceinline__ float fast_sigmoid(float x) {
    return __fdividef(1.0f, 1.0f + __expf(-x));
}
__device__ __forceinline__ float fast_tanh(float x) {
    return 1.0f - 2.0f * __fdividef(1.0f, __expf(2.0f * x) + 1.0f);
}

// ---------------------------------------------------------------------------
// Phase A: gx = x @ Wx^T + bx
// A: [M=16384][K=512], W: [N=2048][K=512] row-major.
// 128x128 block tile, 256 threads, 8x8 micro-tile, K-tile 8, double buffer.
// ---------------------------------------------------------------------------
__global__ __launch_bounds__(256, 2) void gemm_gx(const float* __restrict__ A,
                                                  const float* __restrict__ W,
                                                  const float* __restrict__ bx) {
    __shared__ __align__(16) float As[2][8][132];
    __shared__ __align__(16) float Bs[2][8][132];

    const int bm = blockIdx.y * 128;
    const int bn = blockIdx.x * 128;
    const int tid = threadIdx.x;
    const int lrow = tid >> 1;        // 0..127
    const int lkh = (tid & 1) * 4;    // 0 or 4
    const int ty = tid >> 4;          // 0..15
    const int tx = tid & 15;          // 0..15
    const int m0 = ty * 8;
    const int n0 = tx * 8;

    const float* Aptr = A + (size_t)(bm + lrow) * Isz + lkh;
    const float* Wptr = W + (size_t)(bn + lrow) * Isz + lkh;

    // Prologue: load k-tile 0 into buffer 0.
    {
        float4 a = *(const float4*)Aptr;
        float4 w = *(const float4*)Wptr;
        As[0][lkh + 0][lrow] = a.x;
        As[0][lkh + 1][lrow] = a.y;
        As[0][lkh + 2][lrow] = a.z;
        As[0][lkh + 3][lrow] = a.w;
        Bs[0][lkh + 0][lrow] = w.x;
        Bs[0][lkh + 1][lrow] = w.y;
        Bs[0][lkh + 2][lrow] = w.z;
        Bs[0][lkh + 3][lrow] = w.w;
    }
    __syncthreads();

    unsigned long long acc[8][4];
#pragma unroll
    for (int i = 0; i < 8; i++)
#pragma unroll
        for (int q = 0; q < 4; q++) acc[i][q] = 0ull;

    int cur = 0;
    for (int kt = 1; kt <= 64; kt++) {
        float4 an = make_float4(0.f, 0.f, 0.f, 0.f);
        float4 wn = make_float4(0.f, 0.f, 0.f, 0.f);
        if (kt < 64) {
            an = *(const float4*)(Aptr + kt * 8);
            wn = *(const float4*)(Wptr + kt * 8);
        }
#pragma unroll
        for (int k = 0; k < 8; k++) {
            float4 aLo = *(const float4*)&As[cur][k][m0];
            float4 aHi = *(const float4*)&As[cur][k][m0 + 4];
            ulonglong2 bLo = *(const ulonglong2*)&Bs[cur][k][n0];
            ulonglong2 bHi = *(const ulonglong2*)&Bs[cur][k][n0 + 4];
            float am[8] = {aLo.x, aLo.y, aLo.z, aLo.w,
                           aHi.x, aHi.y, aHi.z, aHi.w};
#pragma unroll
            for (int mm = 0; mm < 8; mm++) {
                unsigned long long ad = pack2(am[mm], am[mm]);
                acc[mm][0] = fma2(bLo.x, ad, acc[mm][0]);
                acc[mm][1] = fma2(bLo.y, ad, acc[mm][1]);
                acc[mm][2] = fma2(bHi.x, ad, acc[mm][2]);
                acc[mm][3] = fma2(bHi.y, ad, acc[mm][3]);
            }
        }
        if (kt < 64) {
            int nxt = cur ^ 1;
            As[nxt][lkh + 0][lrow] = an.x;
            As[nxt][lkh + 1][lrow] = an.y;
            As[nxt][lkh + 2][lrow] = an.z;
            As[nxt][lkh + 3][lrow] = an.w;
            Bs[nxt][lkh + 0][lrow] = wn.x;
            Bs[nxt][lkh + 1][lrow] = wn.y;
            Bs[nxt][lkh + 2][lrow] = wn.z;
            Bs[nxt][lkh + 3][lrow] = wn.w;
        }
        __syncthreads();
        cur ^= 1;
    }

    float4 bxLo = *(const float4*)&bx[bn + n0];
    float4 bxHi = *(const float4*)&bx[bn + n0 + 4];
#pragma unroll
    for (int mm = 0; mm < 8; mm++) {
        float2 p0 = unpack2(acc[mm][0]);
        float2 p1 = unpack2(acc[mm][1]);
        float2 p2 = unpack2(acc[mm][2]);
        float2 p3 = unpack2(acc[mm][3]);
        float4 r0 = make_float4(p0.x + bxLo.x, p0.y + bxLo.y,
                                p1.x + bxLo.z, p1.y + bxLo.w);
        float4 r1 = make_float4(p2.x + bxHi.x, p2.y + bxHi.y,
                                p3.x + bxHi.z, p3.y + bxHi.w);
        float* dst = &g_gx[(size_t)(bm + m0 + mm) * G4 + bn + n0];
        *(float4*)dst = r0;
        *(float4*)(dst + 4) = r1;
    }
}

// ---------------------------------------------------------------------------
// Phase B: persistent scan, 512 threads/block (16 warps), k split 8-way.
//   thread: kq=tid>>6 (0..7), r=tid&63: j=r>>3 (0..7), bg=r&7 -> b0=bg*4
//   smem: w_s[j][k][8] dup pairs (131.3KB) + h_s[k][b] (64KB, also scratch)
// ---------------------------------------------------------------------------
__global__ __launch_bounds__(512, 1) void lstm_scan(const float* __restrict__ Wh,
                                                    const float* __restrict__ bh,
                                                    float* __restrict__ out) {
    extern __shared__ float smem[];
    float* w_s = smem;                 // JPB * WJ floats
    float* h_s = smem + JPB * WJ;      // 512*32 floats (also reduce scratch)

    const int dir = blockIdx.x >> 6;
    const int sub = blockIdx.x & 63;
    const int j0 = sub * JPB;
    const int tid = threadIdx.x;
    const int kq = tid >> 6;       // 0..7
    const int r = tid & 63;
    const int j = r >> 3;          // 0..7
    const int bg = r & 7;          // 0..7
    const int b0 = bg * 4;
    const int k0 = kq * 64;

    // Load Wh tile once, duplicated (w,w) pairs per gate.
    for (int i = tid; i < JPB * 512; i += 512) {
        int j2 = i >> 9;
        int k = i & 511;
        float w0 = Wh[(size_t)(0 * Hsz + j0 + j2) * Hsz + k];
        float w1 = Wh[(size_t)(1 * Hsz + j0 + j2) * Hsz + k];
        float w2 = Wh[(size_t)(2 * Hsz + j0 + j2) * Hsz + k];
        float w3 = Wh[(size_t)(3 * Hsz + j0 + j2) * Hsz + k];
        float* d = &w_s[(size_t)j2 * WJ + k * 8];
        *(float4*)&d[0] = make_float4(w0, w0, w1, w1);
        *(float4*)&d[4] = make_float4(w2, w2, w3, w3);
    }

    float bh_g[4];
#pragma unroll
    for (int g = 0; g < 4; g++) bh_g[g] = bh[g * Hsz + j0 + j];

    unsigned* ctr = &g_ctr[dir];
    float cst[4] = {0.f, 0.f, 0.f, 0.f};
    __syncthreads();

    for (int t = 0; t < Tsz; t++) {
        const int te = dir ? (Tsz - 1 - t) : t;

        // Prefetch gx for owner threads (kq==0): 4 gates x 4 batches.
        float gxr[16];
        if (kq == 0) {
#pragma unroll
            for (int bb = 0; bb < 4; bb++) {
                const float* gp =
                    g_gx + ((size_t)(b0 + bb) * Tsz + te) * G4 + j0 + j;
#pragma unroll
                for (int g = 0; g < 4; g++)
                    gxr[g * 4 + bb] = __ldcg(gp + g * Hsz);
            }
        }

        // Stage h(t) into smem [k][b]: 8 float4 per thread.
        {
            const float4* src = (const float4*)&g_h[dir][t & 1][0];
            float4* dst = (float4*)h_s;
#pragma unroll 4
            for (int i = tid; i < (Hsz * Bsz) / 4; i += 512)
                dst[i] = __ldcg(src + i);
        }
        __syncthreads();

        // k-eighth GEMV: acc[g][batch-pair].
        unsigned long long a00 = 0, a01 = 0, a10 = 0, a11 = 0;
        unsigned long long a20 = 0, a21 = 0, a30 = 0, a31 = 0;
        const float* wp = &w_s[(size_t)j * WJ + k0 * 8];
        const float* hp = &h_s[k0 * 32 + b0];
#pragma unroll 4
        for (int kk = 0; kk < 64; kk++) {
            float4 h4 = *(const float4*)hp;
            ulonglong2 wd01 = *(const ulonglong2*)wp;
            ulonglong2 wd23 = *(const ulonglong2*)(wp + 4);
            unsigned long long hp0 = pack2(h4.x, h4.y);
            unsigned long long hp1 = pack2(h4.z, h4.w);
            a00 = fma2(wd01.x, hp0, a00);
            a01 = fma2(wd01.x, hp1, a01);
            a10 = fma2(wd01.y, hp0, a10);
            a11 = fma2(wd01.y, hp1, a11);
            a20 = fma2(wd23.x, hp0, a20);
            a21 = fma2(wd23.x, hp1, a21);
            a30 = fma2(wd23.y, hp0, a30);
            a31 = fma2(wd23.y, hp1, a31);
            wp += 8;
            hp += 32;
        }
        __syncthreads();  // h_s reads done; safe to reuse as scratch

        // k-split reduction via smem scratch (reuse h_s).
        float* red = h_s;
        if (kq > 0) {
            ulonglong2* d = (ulonglong2*)&red[(size_t)((kq - 1) * 64 + r) * 16];
            d[0] = make_ulonglong2(a00, a01);
            d[1] = make_ulonglong2(a10, a11);
            d[2] = make_ulonglong2(a20, a21);
            d[3] = make_ulonglong2(a30, a31);
        }
        __syncthreads();

        if (kq == 0) {
#pragma unroll
            for (int p = 0; p < 7; p++) {
                const ulonglong2* s =
                    (const ulonglong2*)&red[(size_t)(p * 64 + r) * 16];
                ulonglong2 s0 = s[0], s1 = s[1], s2 = s[2], s3 = s[3];
                a00 = add2(a00, s0.x);
                a01 = add2(a01, s0.y);
                a10 = add2(a10, s1.x);
                a11 = add2(a11, s1.y);
                a20 = add2(a20, s2.x);
                a21 = add2(a21, s2.y);
                a30 = add2(a30, s3.x);
                a31 = add2(a31, s3.y);
            }
            float gate[4][4];
            float2 v;
            v = unpack2(a00); gate[0][0] = v.x; gate[0][1] = v.y;
            v = unpack2(a01); gate[0][2] = v.x; gate[0][3] = v.y;
            v = unpack2(a10); gate[1][0] = v.x; gate[1][1] = v.y;
            v = unpack2(a11); gate[1][2] = v.x; gate[1][3] = v.y;
            v = unpack2(a20); gate[2][0] = v.x; gate[2][1] = v.y;
            v = unpack2(a21); gate[2][2] = v.x; gate[2][3] = v.y;
            v = unpack2(a30); gate[3][0] = v.x; gate[3][1] = v.y;
            v = unpack2(a31); gate[3][2] = v.x; gate[3][3] = v.y;

            float hv[4];
#pragma unroll
            for (int bb = 0; bb < 4; bb++) {
                float gi = gate[0][bb] + gxr[0 * 4 + bb] + bh_g[0];
                float gf = gate[1][bb] + gxr[1 * 4 + bb] + bh_g[1];
                float gg = gate[2][bb] + gxr[2 * 4 + bb] + bh_g[2];
                float go = gate[3][bb] + gxr[3 * 4 + bb] + bh_g[3];
                float it = fast_sigmoid(gi);
                float ft = fast_sigmoid(gf);
                float gt = fast_tanh(gg);
                float ot = fast_sigmoid(go);
                cst[bb] = cst[bb] * ft + it * gt;
                hv[bb] = ot * fast_tanh(cst[bb]);
            }
            *(float4*)&g_h[dir][(t + 1) & 1][(j0 + j) * 32 + b0] =
                make_float4(hv[0], hv[1], hv[2], hv[3]);
#pragma unroll
            for (int bb = 0; bb < 4; bb++)
                out[((size_t)(b0 + bb) * Tsz + t) * (2 * Hsz) + dir * Hsz +
                    j0 + j] = hv[bb];
        }

        // Release h stores, then per-direction barrier.
        __threadfence();
        __syncthreads();
        if (tid == 0) {
            atomicAdd(ctr, 1u);
            unsigned targ = (unsigned)(NBLK_DIR * (t + 1));
            while (*((volatile unsigned*)ctr) < targ) {
            }
        }
        __syncthreads();
    }
}

// ---------------------------------------------------------------------------
extern "C" void kernel_launch(void* const* d_in, const int* in_sizes, int n_in,
                              void* d_out, int out_size) {
    const float* x = (const float*)d_in[0];   // (32,512,512)
    const float* Wx = (const float*)d_in[1];  // (2048,512)
    const float* bx = (const float*)d_in[2];  // (2048)
    const float* Wh = (const float*)d_in[3];  // (2048,512)
    const float* bh = (const float*)d_in[4];  // (2048)
    float* out = (float*)d_out;               // (32,512,1024)

    void* p_h = nullptr;
    void* p_ctr = nullptr;
    cudaGetSymbolAddress(&p_h, g_h);
    cudaGetSymbolAddress(&p_ctr, g_ctr);
    cudaMemsetAsync(p_h, 0, sizeof(g_h), 0);
    cudaMemsetAsync(p_ctr, 0, sizeof(g_ctr), 0);

    // Phase A: input projection GEMM (128x128 tiles).
    dim3 grid(G4 / 128, (Bsz * Tsz) / 128);
    gemm_gx<<<grid, 256>>>(x, Wx, bx);

    // Phase B: persistent scan.
    const int smem_bytes = (JPB * WJ + Hsz * Bsz) * (int)sizeof(float);
    cudaFuncSetAttribute(lstm_scan, cudaFuncAttributeMaxDynamicSharedMemorySize,
                         smem_bytes);
    lstm_scan<<<2 * NBLK_DIR, 512, smem_bytes>>>(Wh, bh, out);
}